// round 1
// baseline (speedup 1.0000x reference)
#include <cuda_runtime.h>
#include <math.h>

#define B        128
#define T_ENC    1024
#define KVS      128
#define EMBED    256
#define VOCAB    30
#define MAX_LEN  250
#define GATES    512     // 4*KVS
#define XDIM     384     // EMBED+KVS

// -------- persistent device scratch (no allocs allowed) --------
__device__ float g_keyT[(size_t)B * KVS * T_ENC];     // [b][k][te]  64 MB
__device__ float g_table[(VOCAB + 1) * GATES];        // [v][g], row VOCAB = bias-only
__device__ float g_WrT[(2 * KVS) * GATES];            // [j][g], j<128 -> ctx weights, j>=128 -> h weights

// -------- shared memory layout (floats) --------
#define TABLE_F  ((VOCAB + 1) * GATES)   // 15872
#define EMB_F    (VOCAB * EMBED)         // 7680
#define HC_F     256
#define C_F      128
#define ATTN_F   1024
#define GATE_F   512
#define PART_F   4096
#define RED_F    40
#define BCP_F    32
#define SMEM_F   (TABLE_F + EMB_F + HC_F + C_F + ATTN_F + GATE_F + PART_F + RED_F + BCP_F)
#define SMEM_BYTES (SMEM_F * 4)

__device__ __forceinline__ float sigm(float x) { return 1.0f / (1.0f + expf(-x)); }

// -------- preprocessing kernels --------
__global__ void transpose_key(const float* __restrict__ key) {
    __shared__ float tile[32][33];
    int b   = blockIdx.z;
    int te0 = blockIdx.x * 32;
    int k0  = blockIdx.y * 32;
    int tx = threadIdx.x, ty = threadIdx.y;       // (32, 8)
    #pragma unroll
    for (int i = ty; i < 32; i += 8)
        tile[i][tx] = key[((size_t)b * T_ENC + te0 + i) * KVS + k0 + tx];
    __syncthreads();
    #pragma unroll
    for (int i = ty; i < 32; i += 8)
        g_keyT[((size_t)b * KVS + k0 + i) * T_ENC + te0 + tx] = tile[tx][i];
}

__global__ void build_table(const float* __restrict__ emb, const float* __restrict__ W_ih,
                            const float* __restrict__ b_ih, const float* __restrict__ b_hh) {
    __shared__ float e_s[EMBED];
    int v = blockIdx.x, g = threadIdx.x;          // 31 blocks x 512 threads
    if (v < VOCAB && g < EMBED) e_s[g] = emb[v * EMBED + g];
    __syncthreads();
    float acc = b_ih[g] + b_hh[g];
    if (v < VOCAB) {
        const float* w = W_ih + (size_t)g * XDIM;
        #pragma unroll 4
        for (int e = 0; e < EMBED; e++) acc += e_s[e] * w[e];
    }
    g_table[v * GATES + g] = acc;
}

__global__ void build_wrt(const float* __restrict__ W_ih, const float* __restrict__ W_hh) {
    int idx = blockIdx.x * blockDim.x + threadIdx.x;   // 0 .. 2*128*512-1, idx = j*512+g
    if (idx >= 2 * KVS * GATES) return;
    int j = idx >> 9, g = idx & 511;
    float w = (j < KVS) ? W_ih[(size_t)g * XDIM + EMBED + j]
                        : W_hh[(size_t)g * KVS + (j - KVS)];
    g_WrT[idx] = w;
}

// -------- main persistent decoder: 1 CTA per batch element --------
__global__ __launch_bounds__(1024, 1)
void decoder_kernel(const float* __restrict__ value, const int* __restrict__ y,
                    const float* __restrict__ emb, const float* __restrict__ b_cp,
                    float* __restrict__ out) {
    extern __shared__ float sm[];
    float* s_table = sm;                         // 15872
    float* s_emb   = s_table + TABLE_F;          // 7680
    float* s_hc    = s_emb + EMB_F;              // [0..127]=h, [128..255]=ctx
    float* s_c     = s_hc + HC_F;                // 128
    float* s_attn  = s_c + C_F;                  // 1024
    float* s_gates = s_attn + ATTN_F;            // 512
    float* s_part  = s_gates + GATE_F;           // 4096 (shared scratch per phase)
    float* s_red   = s_part + PART_F;            // 40
    float* s_bcp   = s_red + RED_F;              // 32

    const int b    = blockIdx.x;
    const int tid  = threadIdx.x;
    const int lane = tid & 31, wid = tid >> 5;

    for (int i = tid; i < TABLE_F; i += 1024) s_table[i] = g_table[i];
    for (int i = tid; i < EMB_F;   i += 1024) s_emb[i]   = emb[i];
    if (tid < VOCAB) s_bcp[tid] = b_cp[tid];
    if (tid < KVS) {
        s_hc[tid] = 0.0f;
        s_c[tid]  = 0.0f;
        s_hc[KVS + tid] = value[(size_t)b * T_ENC * KVS + tid];   // ctx0 = value[b,0,:]
    }
    __syncthreads();

    const float4* V4 = (const float4*)(value + (size_t)b * T_ENC * KVS);
    const float4* K4 = (const float4*)(g_keyT + (size_t)b * KVS * T_ENC);
    const float4* W4 = (const float4*)g_WrT;
    float* out_pred = out + (size_t)b * MAX_LEN * VOCAB;
    float* out_attn = out + (size_t)B * MAX_LEN * VOCAB;   // attentions block (only b==0 writes)

    const int g4  = tid & 127, jc  = tid >> 7;   // gate GEMV decomposition
    const int te4 = tid & 255, kc  = tid >> 8;   // energy decomposition
    const int k4  = tid & 31,  tec = tid >> 5;   // ctx decomposition
    const float* xptr = (jc < 4) ? (s_hc + KVS) : (s_hc - KVS);  // xptr[j]: ctx for j<128, h for j>=128

    for (int t = 0; t < MAX_LEN; t++) {
        // ---- Phase A: gates = table[iv] + [Wctx|Whh] @ [ctx;h] ----
        const int iv = (t == 0) ? VOCAB : y[b * MAX_LEN + t - 1];
        {
            float4 acc = make_float4(0.f, 0.f, 0.f, 0.f);
            const int j0 = jc * 32;
            #pragma unroll 8
            for (int jj = 0; jj < 32; jj++) {
                const int j = j0 + jj;
                const float x = xptr[j];
                const float4 w = W4[j * (GATES / 4) + g4];
                acc.x += w.x * x; acc.y += w.y * x; acc.z += w.z * x; acc.w += w.w * x;
            }
            ((float4*)s_part)[jc * (GATES / 4) + g4] = acc;
        }
        __syncthreads();
        if (tid < GATES) {
            float gv = s_table[iv * GATES + tid];
            #pragma unroll
            for (int c = 0; c < 8; c++) gv += s_part[c * GATES + tid];
            s_gates[tid] = gv;
        }
        __syncthreads();

        // ---- Phase B: LSTM elementwise ----
        if (tid < KVS) {
            const float ig = s_gates[tid];
            const float fg = s_gates[KVS + tid];
            const float gg = s_gates[2 * KVS + tid];
            const float og = s_gates[3 * KVS + tid];
            const float c_new = sigm(fg) * s_c[tid] + sigm(ig) * tanhf(gg);
            const float h_new = sigm(og) * tanhf(c_new);
            s_c[tid]  = c_new;
            s_hc[tid] = h_new;
        }
        __syncthreads();

        // ---- Phase C: energy[te] = keyT[b,:,te] . h ----
        {
            float4 e = make_float4(0.f, 0.f, 0.f, 0.f);
            const int kk0 = kc * 32;
            #pragma unroll 8
            for (int kk = 0; kk < 32; kk++) {
                const float hk = s_hc[kk0 + kk];
                const float4 kv = K4[(kk0 + kk) * (T_ENC / 4) + te4];
                e.x += kv.x * hk; e.y += kv.y * hk; e.z += kv.z * hk; e.w += kv.w * hk;
            }
            ((float4*)s_part)[kc * (T_ENC / 4) + te4] = e;
        }
        __syncthreads();

        // ---- Phase D: softmax over 1024 (te = tid) ----
        const float ev = s_part[tid] + s_part[T_ENC + tid]
                       + s_part[2 * T_ENC + tid] + s_part[3 * T_ENC + tid];
        float m = ev;
        #pragma unroll
        for (int o = 16; o; o >>= 1) m = fmaxf(m, __shfl_xor_sync(0xFFFFFFFFu, m, o));
        if (lane == 0) s_red[wid] = m;
        __syncthreads();
        if (tid < 32) {
            float mm = s_red[tid];
            #pragma unroll
            for (int o = 16; o; o >>= 1) mm = fmaxf(mm, __shfl_xor_sync(0xFFFFFFFFu, mm, o));
            if (tid == 0) s_red[32] = mm;
        }
        __syncthreads();
        const float ex = expf(ev - s_red[32]);
        float su = ex;
        #pragma unroll
        for (int o = 16; o; o >>= 1) su += __shfl_xor_sync(0xFFFFFFFFu, su, o);
        if (lane == 0) s_red[wid] = su;
        __syncthreads();
        if (tid < 32) {
            float ss = s_red[tid];
            #pragma unroll
            for (int o = 16; o; o >>= 1) ss += __shfl_xor_sync(0xFFFFFFFFu, ss, o);
            if (tid == 0) s_red[33] = ss;
        }
        __syncthreads();
        const float attnv = ex / s_red[33];
        s_attn[tid] = attnv;
        if (b == 0) out_attn[(size_t)t * T_ENC + tid] = attnv;
        __syncthreads();

        // ---- Phase E: ctx[k] = sum_te attn[te] * value[b,te,k] ----
        {
            float4 acc = make_float4(0.f, 0.f, 0.f, 0.f);
            const int t0 = tec * 32;
            #pragma unroll 8
            for (int te = 0; te < 32; te++) {
                const float a = s_attn[t0 + te];
                const float4 v = V4[(t0 + te) * (KVS / 4) + k4];
                acc.x += v.x * a; acc.y += v.y * a; acc.z += v.z * a; acc.w += v.w * a;
            }
            ((float4*)s_part)[tec * (KVS / 4) + k4] = acc;
        }
        __syncthreads();
        if (tid < KVS) {
            float cv = 0.f;
            #pragma unroll
            for (int c = 0; c < 32; c++) cv += s_part[c * KVS + tid];
            s_hc[KVS + tid] = cv;
        }
        __syncthreads();

        // ---- Phase F: pred[v] = [h;ctx] . emb[v] + b_cp[v] (warp per vocab) ----
        if (tid < VOCAB * 32) {
            const int v = wid;
            float acc = 0.f;
            #pragma unroll
            for (int e = lane; e < EMBED; e += 32) acc += s_hc[e] * s_emb[v * EMBED + e];
            #pragma unroll
            for (int o = 16; o; o >>= 1) acc += __shfl_xor_sync(0xFFFFFFFFu, acc, o);
            if (lane == 0) out_pred[t * VOCAB + v] = acc + s_bcp[v];
        }
        // next iteration's first __syncthreads (after Phase A partial write) rejoins all warps;
        // Phase F only reads s_hc/s_emb which nothing writes before Phase B of the next step.
    }
}

extern "C" void kernel_launch(void* const* d_in, const int* in_sizes, int n_in,
                              void* d_out, int out_size) {
    const float* key   = (const float*)d_in[0];
    const float* value = (const float*)d_in[1];
    // d_in[2] = encoder_len : unused by the reference
    const int*   y     = (const int*)d_in[3];
    const float* emb   = (const float*)d_in[4];
    const float* W_ih  = (const float*)d_in[5];
    const float* W_hh  = (const float*)d_in[6];
    const float* b_ih  = (const float*)d_in[7];
    const float* b_hh  = (const float*)d_in[8];
    const float* b_cp  = (const float*)d_in[9];
    float* out = (float*)d_out;

    cudaFuncSetAttribute(decoder_kernel, cudaFuncAttributeMaxDynamicSharedMemorySize, SMEM_BYTES);

    dim3 tb(32, 8);
    dim3 tg(T_ENC / 32, KVS / 32, B);
    transpose_key<<<tg, tb>>>(key);
    build_table<<<VOCAB + 1, GATES>>>(emb, W_ih, b_ih, b_hh);
    build_wrt<<<(2 * KVS * GATES) / 256, 256>>>(W_ih, W_hh);
    decoder_kernel<<<B, 1024, SMEM_BYTES>>>(value, y, emb, b_cp, out);
}

// round 2
// speedup vs baseline: 2.2348x; 2.2348x over previous
#include <cuda_runtime.h>
#include <cuda_fp16.h>
#include <math.h>

#define B        128
#define T_ENC    1024
#define KVS      128
#define EMBED    256
#define VOCAB    30
#define MAX_LEN  250
#define GATES    512     // 4*KVS
#define XDIM     384     // EMBED+KVS

// -------- persistent device scratch (no allocs allowed) --------
__device__ float  g_keyT[(size_t)B * KVS * T_ENC];     // [b][k][te]  64 MB (fp32 — attn precision)
__device__ __half g_valH[(size_t)B * T_ENC * KVS];     // [b][te][k]  32 MB (fp16)
__device__ float  g_table[(VOCAB + 1) * GATES];        // [v][g], row VOCAB = bias-only
__device__ float  g_WrT[(2 * KVS) * GATES];            // [j][g], j<128 -> ctx weights, j>=128 -> h weights

// -------- shared memory layout (floats) --------
#define TABLE_F  ((VOCAB + 1) * GATES)   // 15872
#define EMB_F    (VOCAB * EMBED)         // 7680
#define HC_F     256
#define C_F      128
#define ATTN_F   1024
#define GATE_F   512
#define PART_F   4096
#define RED_F    40
#define BCP_F    32
#define SMEM_F   (TABLE_F + EMB_F + HC_F + C_F + ATTN_F + GATE_F + PART_F + RED_F + BCP_F)
#define SMEM_BYTES (SMEM_F * 4)

__device__ __forceinline__ float sigm(float x) { return 1.0f / (1.0f + expf(-x)); }

// -------- preprocessing kernels --------
__global__ void transpose_key(const float* __restrict__ key) {
    __shared__ float tile[32][33];
    int b   = blockIdx.z;
    int te0 = blockIdx.x * 32;
    int k0  = blockIdx.y * 32;
    int tx = threadIdx.x, ty = threadIdx.y;       // (32, 8)
    #pragma unroll
    for (int i = ty; i < 32; i += 8)
        tile[i][tx] = key[((size_t)b * T_ENC + te0 + i) * KVS + k0 + tx];
    __syncthreads();
    #pragma unroll
    for (int i = ty; i < 32; i += 8)
        g_keyT[((size_t)b * KVS + k0 + i) * T_ENC + te0 + tx] = tile[tx][i];
}

__global__ void convert_value(const float* __restrict__ value) {
    size_t i = (size_t)blockIdx.x * blockDim.x + threadIdx.x;
    const size_t n = (size_t)B * T_ENC * KVS;
    // vectorized: each thread converts 4 floats -> 4 halves
    size_t i4 = i * 4;
    if (i4 < n) {
        float4 v = *(const float4*)(value + i4);
        __half2* dst = (__half2*)(g_valH + i4);
        dst[0] = __floats2half2_rn(v.x, v.y);
        dst[1] = __floats2half2_rn(v.z, v.w);
    }
}

__global__ void build_table(const float* __restrict__ emb, const float* __restrict__ W_ih,
                            const float* __restrict__ b_ih, const float* __restrict__ b_hh) {
    __shared__ float e_s[EMBED];
    int v = blockIdx.x, g = threadIdx.x;          // 31 blocks x 512 threads
    if (v < VOCAB && g < EMBED) e_s[g] = emb[v * EMBED + g];
    __syncthreads();
    float acc = b_ih[g] + b_hh[g];
    if (v < VOCAB) {
        const float* w = W_ih + (size_t)g * XDIM;
        #pragma unroll 4
        for (int e = 0; e < EMBED; e++) acc += e_s[e] * w[e];
    }
    g_table[v * GATES + g] = acc;
}

__global__ void build_wrt(const float* __restrict__ W_ih, const float* __restrict__ W_hh) {
    int idx = blockIdx.x * blockDim.x + threadIdx.x;   // 0 .. 2*128*512-1, idx = j*512+g
    if (idx >= 2 * KVS * GATES) return;
    int j = idx >> 9, g = idx & 511;
    float w = (j < KVS) ? W_ih[(size_t)g * XDIM + EMBED + j]
                        : W_hh[(size_t)g * KVS + (j - KVS)];
    g_WrT[idx] = w;
}

// -------- main persistent decoder: 1 CTA per batch element --------
__global__ __launch_bounds__(1024, 1)
void decoder_kernel(const float* __restrict__ value, const int* __restrict__ y,
                    const float* __restrict__ emb, const float* __restrict__ b_cp,
                    float* __restrict__ out) {
    extern __shared__ float sm[];
    float* s_table = sm;                         // 15872
    float* s_emb   = s_table + TABLE_F;          // 7680
    float* s_hc    = s_emb + EMB_F;              // [0..127]=h, [128..255]=ctx
    float* s_c     = s_hc + HC_F;                // 128
    float* s_attn  = s_c + C_F;                  // 1024
    float* s_gates = s_attn + ATTN_F;            // 512
    float* s_part  = s_gates + GATE_F;           // 4096 (shared scratch per phase)
    float* s_red   = s_part + PART_F;            // 40
    float* s_bcp   = s_red + RED_F;              // 32

    const int b    = blockIdx.x;
    const int tid  = threadIdx.x;
    const int lane = tid & 31, wid = tid >> 5;

    for (int i = tid; i < TABLE_F; i += 1024) s_table[i] = g_table[i];
    for (int i = tid; i < EMB_F;   i += 1024) s_emb[i]   = emb[i];
    if (tid < VOCAB) s_bcp[tid] = b_cp[tid];
    if (tid < KVS) {
        s_hc[tid] = 0.0f;
        s_c[tid]  = 0.0f;
        s_hc[KVS + tid] = value[(size_t)b * T_ENC * KVS + tid];   // ctx0 = value[b,0,:] (exact fp32)
    }
    __syncthreads();

    const uint2*  V2 = (const uint2*)(g_valH + (size_t)b * T_ENC * KVS);  // 4 halves per load
    const float4* K4 = (const float4*)(g_keyT + (size_t)b * KVS * T_ENC);
    const float4* W4 = (const float4*)g_WrT;
    float* out_pred = out + (size_t)b * MAX_LEN * VOCAB;
    float* out_attn = out + (size_t)B * MAX_LEN * VOCAB;   // attentions block (only b==0 writes)

    const int g4  = tid & 127, jc  = tid >> 7;   // gate GEMV decomposition
    const int te4 = tid & 255, kc  = tid >> 8;   // energy decomposition
    const int k4  = tid & 31,  tec = tid >> 5;   // ctx decomposition
    const float* xptr = (jc < 4) ? (s_hc + KVS) : (s_hc - KVS);  // xptr[j]: ctx for j<128, h for j>=128

    for (int t = 0; t < MAX_LEN; t++) {
        // ---- Phase A: gates = table[iv] + [Wctx|Whh] @ [ctx;h] ----
        const int iv = (t == 0) ? VOCAB : y[b * MAX_LEN + t - 1];
        {
            float4 acc = make_float4(0.f, 0.f, 0.f, 0.f);
            const int j0 = jc * 32;
            #pragma unroll 8
            for (int jj = 0; jj < 32; jj++) {
                const int j = j0 + jj;
                const float x = xptr[j];
                const float4 w = W4[j * (GATES / 4) + g4];
                acc.x += w.x * x; acc.y += w.y * x; acc.z += w.z * x; acc.w += w.w * x;
            }
            ((float4*)s_part)[jc * (GATES / 4) + g4] = acc;
        }
        __syncthreads();
        if (tid < GATES) {
            float gv = s_table[iv * GATES + tid];
            #pragma unroll
            for (int c = 0; c < 8; c++) gv += s_part[c * GATES + tid];
            s_gates[tid] = gv;
        }
        __syncthreads();

        // ---- Phase B: LSTM elementwise ----
        if (tid < KVS) {
            const float ig = s_gates[tid];
            const float fg = s_gates[KVS + tid];
            const float gg = s_gates[2 * KVS + tid];
            const float og = s_gates[3 * KVS + tid];
            const float c_new = sigm(fg) * s_c[tid] + sigm(ig) * tanhf(gg);
            const float h_new = sigm(og) * tanhf(c_new);
            s_c[tid]  = c_new;
            s_hc[tid] = h_new;
        }
        __syncthreads();

        // ---- Phase C: energy[te] = keyT[b,:,te] . h (fp32 for attn accuracy) ----
        {
            float4 e = make_float4(0.f, 0.f, 0.f, 0.f);
            const int kk0 = kc * 32;
            #pragma unroll 8
            for (int kk = 0; kk < 32; kk++) {
                const float hk = s_hc[kk0 + kk];
                const float4 kv = K4[(kk0 + kk) * (T_ENC / 4) + te4];
                e.x += kv.x * hk; e.y += kv.y * hk; e.z += kv.z * hk; e.w += kv.w * hk;
            }
            ((float4*)s_part)[kc * (T_ENC / 4) + te4] = e;
        }
        __syncthreads();

        // ---- Phase D: softmax over 1024 (te = tid) ----
        const float ev = s_part[tid] + s_part[T_ENC + tid]
                       + s_part[2 * T_ENC + tid] + s_part[3 * T_ENC + tid];
        float m = ev;
        #pragma unroll
        for (int o = 16; o; o >>= 1) m = fmaxf(m, __shfl_xor_sync(0xFFFFFFFFu, m, o));
        if (lane == 0) s_red[wid] = m;
        __syncthreads();
        if (tid < 32) {
            float mm = s_red[tid];
            #pragma unroll
            for (int o = 16; o; o >>= 1) mm = fmaxf(mm, __shfl_xor_sync(0xFFFFFFFFu, mm, o));
            if (tid == 0) s_red[32] = mm;
        }
        __syncthreads();
        const float ex = expf(ev - s_red[32]);
        float su = ex;
        #pragma unroll
        for (int o = 16; o; o >>= 1) su += __shfl_xor_sync(0xFFFFFFFFu, su, o);
        if (lane == 0) s_red[wid] = su;
        __syncthreads();
        if (tid < 32) {
            float ss = s_red[tid];
            #pragma unroll
            for (int o = 16; o; o >>= 1) ss += __shfl_xor_sync(0xFFFFFFFFu, ss, o);
            if (tid == 0) s_red[33] = ss;
        }
        __syncthreads();
        const float attnv = ex / s_red[33];
        s_attn[tid] = attnv;
        if (b == 0) out_attn[(size_t)t * T_ENC + tid] = attnv;
        __syncthreads();

        // ---- Phase E: ctx[k] = sum_te attn[te] * value[b,te,k]  (value in fp16) ----
        {
            float4 acc = make_float4(0.f, 0.f, 0.f, 0.f);
            const int t0 = tec * 32;
            #pragma unroll 8
            for (int te = 0; te < 32; te++) {
                const float a = s_attn[t0 + te];
                const uint2 raw = V2[(t0 + te) * (KVS / 4) + k4];
                const __half2 v01 = *(const __half2*)&raw.x;
                const __half2 v23 = *(const __half2*)&raw.y;
                const float2 f01 = __half22float2(v01);
                const float2 f23 = __half22float2(v23);
                acc.x += f01.x * a; acc.y += f01.y * a; acc.z += f23.x * a; acc.w += f23.y * a;
            }
            ((float4*)s_part)[tec * (KVS / 4) + k4] = acc;
        }
        __syncthreads();
        if (tid < KVS) {
            float cv = 0.f;
            #pragma unroll
            for (int c = 0; c < 32; c++) cv += s_part[c * KVS + tid];
            s_hc[KVS + tid] = cv;
        }
        __syncthreads();

        // ---- Phase F: pred[v] = [h;ctx] . emb[v] + b_cp[v] (warp per vocab) ----
        if (tid < VOCAB * 32) {
            const int v = wid;
            float acc = 0.f;
            #pragma unroll
            for (int e = lane; e < EMBED; e += 32) acc += s_hc[e] * s_emb[v * EMBED + e];
            #pragma unroll
            for (int o = 16; o; o >>= 1) acc += __shfl_xor_sync(0xFFFFFFFFu, acc, o);
            if (lane == 0) out_pred[t * VOCAB + v] = acc + s_bcp[v];
        }
        // next iteration's first __syncthreads rejoins all warps; Phase F reads only
        // s_hc/s_emb which nothing writes before Phase B of the next step.
    }
}

extern "C" void kernel_launch(void* const* d_in, const int* in_sizes, int n_in,
                              void* d_out, int out_size) {
    const float* key   = (const float*)d_in[0];
    const float* value = (const float*)d_in[1];
    // d_in[2] = encoder_len : unused by the reference
    const int*   y     = (const int*)d_in[3];
    const float* emb   = (const float*)d_in[4];
    const float* W_ih  = (const float*)d_in[5];
    const float* W_hh  = (const float*)d_in[6];
    const float* b_ih  = (const float*)d_in[7];
    const float* b_hh  = (const float*)d_in[8];
    const float* b_cp  = (const float*)d_in[9];
    float* out = (float*)d_out;

    cudaFuncSetAttribute(decoder_kernel, cudaFuncAttributeMaxDynamicSharedMemorySize, SMEM_BYTES);

    dim3 tb(32, 8);
    dim3 tg(T_ENC / 32, KVS / 32, B);
    transpose_key<<<tg, tb>>>(key);
    {
        const size_t n4 = ((size_t)B * T_ENC * KVS) / 4;
        convert_value<<<(int)((n4 + 255) / 256), 256>>>(value);
    }
    build_table<<<VOCAB + 1, GATES>>>(emb, W_ih, b_ih, b_hh);
    build_wrt<<<(2 * KVS * GATES) / 256, 256>>>(W_ih, W_hh);
    decoder_kernel<<<B, 1024, SMEM_BYTES>>>(value, y, emb, b_cp, out);
}